// round 10
// baseline (speedup 1.0000x reference)
#include <cuda_runtime.h>
#include <math.h>

#define FULLMASK 0xffffffffu

// Scratch (device globals — no allocation allowed)
__device__ __align__(16) float g_A[8][16384];       // [b][r*2048+d]
__device__ __align__(16) float g_B[8][16384];       // [b][r*2048+o], pre-scaled by 2.0

union F2U { float2 f; unsigned long long u; };

__device__ __forceinline__ float2 ffma2(float2 a, float2 b, float2 c) {
    F2U ua, ub, uc, ur;
    ua.f = a; ub.f = b; uc.f = c;
    asm("fma.rn.f32x2 %0, %1, %2, %3;"
        : "=l"(ur.u) : "l"(ua.u), "l"(ub.u), "l"(uc.u));
    return ur.f;
}

// ---------------------------------------------------------------------------
// Kernel 1 (fused gate + A/B build). Grid (16 chunks, 8 batches), 256 thr.
// Warp 0 recomputes the gating MLP for batch b while all threads prefetch
// Wa/Wb (independent of gate). One sync, then A = g.Wa, B = 2*g.Wb.
// ---------------------------------------------------------------------------
__global__ __launch_bounds__(256) void gab_kernel(
        const float* __restrict__ ctr,
        const float* __restrict__ gamma,
        const float* __restrict__ beta,
        const float* __restrict__ W1,
        const float* __restrict__ b1,
        const float* __restrict__ W2,
        const float* __restrict__ b2,
        const float4* __restrict__ Wa,
        const float4* __restrict__ Wb) {
    __shared__ float4 gate_s;
    int b = blockIdx.y;
    int chunk = blockIdx.x;           // 0..15
    int t = threadIdx.x;

    int base = chunk * 1024;
    float4 wa[4], wb[4];
    #pragma unroll
    for (int k = 0; k < 4; k++) {
        int e = base + (k << 8) + t;
        wa[k] = Wa[e];
        wb[k] = Wb[e];
    }

    if (t < 32) {
        int lane = t;
        float c = ctr[b * 32 + lane];
        float mu = c;
        #pragma unroll
        for (int o = 16; o; o >>= 1) mu += __shfl_xor_sync(FULLMASK, mu, o);
        mu *= 0.03125f;
        float d = c - mu;
        float v = d * d;
        #pragma unroll
        for (int o = 16; o; o >>= 1) v += __shfl_xor_sync(FULLMASK, v, o);
        v *= 0.03125f;
        float z = d * rsqrtf(v + 1e-5f) * gamma[lane] + beta[lane];

        int j1 = lane, j2 = lane + 32;
        bool v2 = (j2 < 60);
        float s1 = b1[j1];
        float s2 = v2 ? b1[j2] : 0.f;
        #pragma unroll
        for (int k = 0; k < 32; k++) {
            float zk = __shfl_sync(FULLMASK, z, k);
            s1 += W1[j1 * 32 + k] * zk;
            if (v2) s2 += W1[j2 * 32 + k] * zk;
        }
        float h1 = fmaxf(s1, 0.f);
        float h2 = v2 ? fmaxf(s2, 0.f) : 0.f;

        float p[4];
        #pragma unroll
        for (int i = 0; i < 4; i++) {
            float s = W2[i * 60 + j1] * h1;
            if (v2) s += W2[i * 60 + j2] * h2;
            #pragma unroll
            for (int o = 16; o; o >>= 1) s += __shfl_xor_sync(FULLMASK, s, o);
            p[i] = s;
        }
        if (lane == 0) {
            float mx = fmaxf(fmaxf(p[0] + b2[0], p[1] + b2[1]),
                             fmaxf(p[2] + b2[2], p[3] + b2[3]));
            float e0 = expf(p[0] + b2[0] - mx);
            float e1 = expf(p[1] + b2[1] - mx);
            float e2 = expf(p[2] + b2[2] - mx);
            float e3 = expf(p[3] + b2[3] - mx);
            float inv = 1.f / (e0 + e1 + e2 + e3);
            gate_s = make_float4(e0 * inv, e1 * inv, e2 * inv, e3 * inv);
        }
    }
    __syncthreads();

    float4 g = gate_s;
    #pragma unroll
    for (int k = 0; k < 4; k++) {
        int e = base + (k << 8) + t;
        g_A[b][e] = g.x * wa[k].x + g.y * wa[k].y + g.z * wa[k].z + g.w * wa[k].w;
        g_B[b][e] = 2.0f * (g.x * wb[k].x + g.y * wb[k].y + g.z * wb[k].z + g.w * wb[k].w);
    }
}

// ---------------------------------------------------------------------------
// Kernel 2 (fused xa + out), rank-split for occupancy:
// Block = 16 rows of batch b, 8 warps. Warp w: rows (w>>1)*4..+4 of the
// block, ranks (w&1)*4..+4. acc = 4 rows x 4 ranks x float2 = 32 regs.
// Ranks are disjoint across warp pairs -> warp shuffle-reduce directly
// yields final xa values (no cross-warp combine).
// Phase 2: two column-halves; B half in 32 regs, xa broadcast from smem,
// streaming float4 stores.
// __launch_bounds__(256,3): 3 blocks/SM (smem 64.5KB, regs<=85).
// ---------------------------------------------------------------------------
__global__ __launch_bounds__(256, 3) void fused_kernel(const float* __restrict__ x,
                                                       float* __restrict__ out) {
    extern __shared__ float smem[];
    float4* A_s  = (float4*)smem;            // 4096 float4 = 64 KB
    float4* xa_s = (float4*)(smem + 16384);  // 32 float4 (16 rows x 8 floats)

    int b = blockIdx.y;
    int row0b = blockIdx.x * 16;
    int t = threadIdx.x;

    const float4* Ag = (const float4*)&g_A[b][0];
    #pragma unroll
    for (int i = 0; i < 16; i++) A_s[(i << 8) + t] = Ag[(i << 8) + t];
    __syncthreads();

    int warp = t >> 5;
    int lane = t & 31;
    int rowg  = warp >> 1;        // 0..3  (4 rows each)
    int rhalf = warp & 1;         // 0..1  (ranks rhalf*4 .. +4)
    int row0 = row0b + rowg * 4;
    const float4* xrow = (const float4*)(x + (((size_t)b << 11) + row0) * 2048);
    const float4* A_w = A_s + (rhalf << 11);   // start of this warp's 4 ranks

    float2 acc[4][4];
    #pragma unroll
    for (int j = 0; j < 4; j++)
        #pragma unroll
        for (int r = 0; r < 4; r++) acc[j][r] = make_float2(0.f, 0.f);

    #pragma unroll 2
    for (int i = 0; i < 16; i++) {
        int d4 = (i << 5) + lane;
        float4 xv0 = __ldcs(&xrow[d4]);
        float4 xv1 = __ldcs(&xrow[512 + d4]);
        float4 xv2 = __ldcs(&xrow[1024 + d4]);
        float4 xv3 = __ldcs(&xrow[1536 + d4]);
        #pragma unroll
        for (int r = 0; r < 4; r++) {
            float4 av = A_w[(r << 9) + d4];
            float2 alo = make_float2(av.x, av.y);
            float2 ahi = make_float2(av.z, av.w);
            acc[0][r] = ffma2(make_float2(xv0.x, xv0.y), alo, acc[0][r]);
            acc[0][r] = ffma2(make_float2(xv0.z, xv0.w), ahi, acc[0][r]);
            acc[1][r] = ffma2(make_float2(xv1.x, xv1.y), alo, acc[1][r]);
            acc[1][r] = ffma2(make_float2(xv1.z, xv1.w), ahi, acc[1][r]);
            acc[2][r] = ffma2(make_float2(xv2.x, xv2.y), alo, acc[2][r]);
            acc[2][r] = ffma2(make_float2(xv2.z, xv2.w), ahi, acc[2][r]);
            acc[3][r] = ffma2(make_float2(xv3.x, xv3.y), alo, acc[3][r]);
            acc[3][r] = ffma2(make_float2(xv3.z, xv3.w), ahi, acc[3][r]);
        }
    }

    #pragma unroll
    for (int j = 0; j < 4; j++) {
        float s[4];
        #pragma unroll
        for (int r = 0; r < 4; r++) {
            float v = acc[j][r].x + acc[j][r].y;
            #pragma unroll
            for (int o = 16; o; o >>= 1) v += __shfl_xor_sync(FULLMASK, v, o);
            s[r] = v;
        }
        if (lane == 0)
            xa_s[((rowg << 2) + j) * 2 + rhalf] = make_float4(s[0], s[1], s[2], s[3]);
    }
    __syncthreads();

    // Phase 2: out[row][o] = sum_r xa[row][r] * B[b][r][o]  (B pre-scaled)
    const float4* Bg = (const float4*)&g_B[b][0];  // [8][512] float4
    float4* orow = (float4*)(out + (((size_t)b << 11) + row0b) * 2048);

    #pragma unroll
    for (int h = 0; h < 2; h++) {
        int col4 = (h << 8) + t;     // float4 column index (0..511)
        float4 Bv[8];
        #pragma unroll
        for (int r = 0; r < 8; r++) Bv[r] = Bg[(r << 9) + col4];

        #pragma unroll 4
        for (int row = 0; row < 16; row++) {
            float4 xa0 = xa_s[row * 2];
            float4 xa1 = xa_s[row * 2 + 1];
            float xr[8] = {xa0.x, xa0.y, xa0.z, xa0.w, xa1.x, xa1.y, xa1.z, xa1.w};
            float2 a0 = make_float2(0.f, 0.f), a1 = a0;
            #pragma unroll
            for (int r = 0; r < 8; r++) {
                float2 s = make_float2(xr[r], xr[r]);
                a0 = ffma2(s, make_float2(Bv[r].x, Bv[r].y), a0);
                a1 = ffma2(s, make_float2(Bv[r].z, Bv[r].w), a1);
            }
            __stcs(&orow[(row << 9) + col4], make_float4(a0.x, a0.y, a1.x, a1.y));
        }
    }
}

// ---------------------------------------------------------------------------
extern "C" void kernel_launch(void* const* d_in, const int* in_sizes, int n_in,
                              void* d_out, int out_size) {
    const float* x   = (const float*)d_in[0];
    const float* ctr = (const float*)d_in[1];
    const float* gam = (const float*)d_in[2];
    const float* bet = (const float*)d_in[3];
    const float* W1  = (const float*)d_in[4];
    const float* b1  = (const float*)d_in[5];
    const float* W2  = (const float*)d_in[6];
    const float* b2  = (const float*)d_in[7];
    const float* Wa  = (const float*)d_in[8];
    const float* Wb  = (const float*)d_in[9];
    float* out = (float*)d_out;

    cudaFuncSetAttribute(fused_kernel, cudaFuncAttributeMaxDynamicSharedMemorySize, 66048);

    gab_kernel<<<dim3(16, 8), 256>>>(ctr, gam, bet, W1, b1, W2, b2,
                                     (const float4*)Wa, (const float4*)Wb);
    fused_kernel<<<dim3(128, 8), 256, 66048>>>(x, out);
}